// round 2
// baseline (speedup 1.0000x reference)
#include <cuda_runtime.h>

#define VOCAB 10000
#define EMB   16
#define HID   32
#define NCLS  2
#define BATCH 4096
#define SEQ   512

// Projected embedding table: proj[t][h] = sum_e emb[t][e]*W_ih[h][e] + b_ih[h] + b_hh[h]
__device__ float g_proj[VOCAB * HID];

__global__ void build_proj_kernel(const float* __restrict__ emb,
                                  const float* __restrict__ W_ih,
                                  const float* __restrict__ b_ih,
                                  const float* __restrict__ b_hh) {
    int t    = blockIdx.x * (blockDim.x >> 5) + (threadIdx.x >> 5);
    int lane = threadIdx.x & 31;
    if (t >= VOCAB) return;
    float acc = __ldg(b_ih + lane) + __ldg(b_hh + lane);
#pragma unroll
    for (int e = 0; e < EMB; e++) {
        // emb load is warp-uniform (broadcast); W_ih row is per-lane, L1-resident.
        acc = fmaf(__ldg(emb + t * EMB + e), __ldg(W_ih + lane * EMB + e), acc);
    }
    g_proj[t * HID + lane] = acc;
}

// One warp per batch element; lane = hidden unit.
// h broadcast each step via double-buffered shared memory (1 syncwarp/step).
__global__ void __launch_bounds__(64) rnn_step_kernel(
    const int* __restrict__ x,          // tokens are int32 (JAX default int)
    const float* __restrict__ W_hh,
    const float* __restrict__ W_fc,
    const float* __restrict__ b_fc,
    float* __restrict__ out) {

    int wl   = threadIdx.x >> 5;
    int lane = threadIdx.x & 31;
    int b    = blockIdx.x * 2 + wl;

    __shared__ __align__(16) float hbuf[2][2][HID];

    // W_hh row for this lane's output unit (kept in registers).
    float w[HID];
#pragma unroll
    for (int j = 0; j < HID; j++) w[j] = __ldg(W_hh + lane * HID + j);

    const int* xb = x + b * SEQ;
    float h = 0.0f;

    for (int c = 0; c < SEQ / 32; c++) {
        // 32 tokens per chunk, one per lane (128B coalesced LDG).
        int tok = xb[c * 32 + lane];
#pragma unroll 4
        for (int j = 0; j < 32; j++) {
            int t = __shfl_sync(0xffffffffu, tok, j);
            float xp = __ldg(&g_proj[t * HID + lane]);   // 128B coalesced, L2-resident

            float(&hb)[HID] = hbuf[wl][j & 1];
            hb[lane] = h;
            __syncwarp();

            float acc = xp;
#pragma unroll
            for (int k = 0; k < HID; k += 4) {
                float4 hv = *(const float4*)&hb[k];      // broadcast LDS.128
                acc = fmaf(hv.x, w[k + 0], acc);
                acc = fmaf(hv.y, w[k + 1], acc);
                acc = fmaf(hv.z, w[k + 2], acc);
                acc = fmaf(hv.w, w[k + 3], acc);
            }
            h = tanhf(acc);
        }
    }

    // Classifier head: two warp reductions.
    float v0 = h * __ldg(W_fc + lane);
    float v1 = h * __ldg(W_fc + HID + lane);
#pragma unroll
    for (int o = 16; o > 0; o >>= 1) {
        v0 += __shfl_xor_sync(0xffffffffu, v0, o);
        v1 += __shfl_xor_sync(0xffffffffu, v1, o);
    }
    if (lane == 0) {
        out[b * NCLS + 0] = v0 + __ldg(b_fc + 0);
        out[b * NCLS + 1] = v1 + __ldg(b_fc + 1);
    }
}

extern "C" void kernel_launch(void* const* d_in, const int* in_sizes, int n_in,
                              void* d_out, int out_size) {
    const int*   x    = (const int*)d_in[0];
    const float* emb  = (const float*)d_in[1];
    const float* W_ih = (const float*)d_in[2];
    const float* W_hh = (const float*)d_in[3];
    const float* b_ih = (const float*)d_in[4];
    const float* b_hh = (const float*)d_in[5];
    const float* W_fc = (const float*)d_in[6];
    const float* b_fc = (const float*)d_in[7];
    float* out = (float*)d_out;

    build_proj_kernel<<<(VOCAB + 7) / 8, 256>>>(emb, W_ih, b_ih, b_hh);
    rnn_step_kernel<<<BATCH / 2, 64>>>(x, W_hh, W_fc, b_fc, out);
}

// round 3
// speedup vs baseline: 1.0453x; 1.0453x over previous
#include <cuda_runtime.h>

#define VOCAB 10000
#define EMB   16
#define HID   32
#define NCLS  2
#define BATCH 4096
#define SEQ   512

typedef unsigned long long ull;

// Projected embedding table: proj[t][h] = sum_e emb[t][e]*W_ih[h][e] + b_ih[h] + b_hh[h]
__device__ float g_proj[VOCAB * HID];

__global__ void build_proj_kernel(const float* __restrict__ emb,
                                  const float* __restrict__ W_ih,
                                  const float* __restrict__ b_ih,
                                  const float* __restrict__ b_hh) {
    int t    = blockIdx.x * (blockDim.x >> 5) + (threadIdx.x >> 5);
    int lane = threadIdx.x & 31;
    if (t >= VOCAB) return;
    float acc = __ldg(b_ih + lane) + __ldg(b_hh + lane);
#pragma unroll
    for (int e = 0; e < EMB; e++) {
        acc = fmaf(__ldg(emb + t * EMB + e), __ldg(W_ih + lane * EMB + e), acc);
    }
    g_proj[t * HID + lane] = acc;
}

// tanh(x) = 1 - 2/(e^{2x}+1), branch-free via MUFU ex2/rcp.
// Saturates correctly at +-inf; abs err ~1e-6.
__device__ __forceinline__ float fast_tanh(float x) {
    float e;
    asm("ex2.approx.f32 %0, %1;" : "=f"(e) : "f"(x * 2.8853900817779268f));
    float r;
    asm("rcp.approx.f32 %0, %1;" : "=f"(r) : "f"(e + 1.0f));
    return fmaf(-2.0f, r, 1.0f);
}

__device__ __forceinline__ ull pack2(float lo, float hi) {
    ull u;
    asm("mov.b64 %0, {%1, %2};" : "=l"(u) : "f"(lo), "f"(hi));
    return u;
}
__device__ __forceinline__ void unpack2(ull u, float& lo, float& hi) {
    asm("mov.b64 {%0, %1}, %2;" : "=f"(lo), "=f"(hi) : "l"(u));
}
__device__ __forceinline__ ull fma2(ull a, ull b, ull c) {
    asm("fma.rn.f32x2 %0, %1, %2, %3;" : "=l"(c) : "l"(a), "l"(b), "l"(c));
    return c;
}
__device__ __forceinline__ ull add2(ull a, ull b) {
    ull c;
    asm("add.rn.f32x2 %0, %1, %2;" : "=l"(c) : "l"(a), "l"(b));
    return c;
}

// One warp per batch element; lane = hidden unit.
// h broadcast via double-buffered shared memory; recurrent matvec in packed f32x2 FMAs.
__global__ void __launch_bounds__(128) rnn_step_kernel(
    const int* __restrict__ x,
    const float* __restrict__ W_hh,
    const float* __restrict__ W_fc,
    const float* __restrict__ b_fc,
    float* __restrict__ out) {

    int wl   = threadIdx.x >> 5;
    int lane = threadIdx.x & 31;
    int b    = blockIdx.x * 4 + wl;

    __shared__ __align__(16) float hbuf[4][2][HID];

    // W_hh row for this lane, packed into 16 f32x2 registers.
    ull w2[HID / 2];
#pragma unroll
    for (int j = 0; j < HID / 2; j++) {
        float2 wf = __ldg((const float2*)(W_hh + lane * HID) + j);
        w2[j] = pack2(wf.x, wf.y);
    }

    const int* xb = x + b * SEQ;

    // init h buffer for step 0
    hbuf[wl][0][lane] = 0.0f;
    float h = 0.0f;

    // prefetch step-0 input projection
    int t0 = __ldg(xb);                               // uniform-address, L1-resident
    float xp = __ldg(&g_proj[t0 * HID + lane]);       // 128B coalesced, L2-resident

#pragma unroll 2
    for (int s = 0; s < SEQ; s++) {
        // prefetch NEXT step's proj row (hides L2 latency behind this step's chain)
        float xp_next = 0.0f;
        if (s + 1 < SEQ) {
            int tn = __ldg(&xb[s + 1]);
            xp_next = __ldg(&g_proj[tn * HID + lane]);
        }

        __syncwarp();                                 // orders prev STS before reads
        const ull* hb = (const ull*)hbuf[wl][s & 1];

        ull a0 = 0, a1 = 0, a2 = 0, a3 = 0;
#pragma unroll
        for (int k = 0; k < HID / 2; k += 4) {        // 16 LDS.64 broadcasts + 16 packed FMA
            a0 = fma2(hb[k + 0], w2[k + 0], a0);
            a1 = fma2(hb[k + 1], w2[k + 1], a1);
            a2 = fma2(hb[k + 2], w2[k + 2], a2);
            a3 = fma2(hb[k + 3], w2[k + 3], a3);
        }
        ull ssum = add2(add2(a0, a1), add2(a2, a3));
        float lo, hi;
        unpack2(ssum, lo, hi);

        h = fast_tanh(xp + lo + hi);

        hbuf[wl][(s + 1) & 1][lane] = h;              // for next step (other buffer)
        xp = xp_next;
    }

    // Classifier head: two warp reductions.
    float v0 = h * __ldg(W_fc + lane);
    float v1 = h * __ldg(W_fc + HID + lane);
#pragma unroll
    for (int o = 16; o > 0; o >>= 1) {
        v0 += __shfl_xor_sync(0xffffffffu, v0, o);
        v1 += __shfl_xor_sync(0xffffffffu, v1, o);
    }
    if (lane == 0) {
        out[b * NCLS + 0] = v0 + __ldg(b_fc + 0);
        out[b * NCLS + 1] = v1 + __ldg(b_fc + 1);
    }
}

extern "C" void kernel_launch(void* const* d_in, const int* in_sizes, int n_in,
                              void* d_out, int out_size) {
    const int*   x    = (const int*)d_in[0];
    const float* emb  = (const float*)d_in[1];
    const float* W_ih = (const float*)d_in[2];
    const float* W_hh = (const float*)d_in[3];
    const float* b_ih = (const float*)d_in[4];
    const float* b_hh = (const float*)d_in[5];
    const float* W_fc = (const float*)d_in[6];
    const float* b_fc = (const float*)d_in[7];
    float* out = (float*)d_out;

    build_proj_kernel<<<(VOCAB + 7) / 8, 256>>>(emb, W_ih, b_ih, b_hh);
    rnn_step_kernel<<<BATCH / 4, 128>>>(x, W_hh, W_fc, b_fc, out);
}

// round 4
// speedup vs baseline: 1.0660x; 1.0198x over previous
#include <cuda_runtime.h>

#define VOCAB 10000
#define EMB   16
#define HID   32
#define NCLS  2
#define BATCH 4096
#define SEQ   512

typedef unsigned long long ull;

// Projected embedding table: proj[t][h] = sum_e emb[t][e]*W_ih[h][e] + b_ih[h] + b_hh[h]
__device__ float g_proj[VOCAB * HID];

__global__ void build_proj_kernel(const float* __restrict__ emb,
                                  const float* __restrict__ W_ih,
                                  const float* __restrict__ b_ih,
                                  const float* __restrict__ b_hh) {
    int t    = blockIdx.x * (blockDim.x >> 5) + (threadIdx.x >> 5);
    int lane = threadIdx.x & 31;
    if (t >= VOCAB) return;
    float acc = __ldg(b_ih + lane) + __ldg(b_hh + lane);
#pragma unroll
    for (int e = 0; e < EMB; e++) {
        acc = fmaf(__ldg(emb + t * EMB + e), __ldg(W_ih + lane * EMB + e), acc);
    }
    g_proj[t * HID + lane] = acc;
}

// tanh(x) = 1 - 2/(e^{2x}+1), branch-free via MUFU ex2/rcp. abs err ~1e-6.
__device__ __forceinline__ float fast_tanh(float x) {
    float e;
    asm("ex2.approx.f32 %0, %1;" : "=f"(e) : "f"(x * 2.8853900817779268f));
    float r;
    asm("rcp.approx.f32 %0, %1;" : "=f"(r) : "f"(e + 1.0f));
    return fmaf(-2.0f, r, 1.0f);
}

__device__ __forceinline__ ull pack2(float lo, float hi) {
    ull u;
    asm("mov.b64 %0, {%1, %2};" : "=l"(u) : "f"(lo), "f"(hi));
    return u;
}
__device__ __forceinline__ void unpack2(ull u, float& lo, float& hi) {
    asm("mov.b64 {%0, %1}, %2;" : "=f"(lo), "=f"(hi) : "l"(u));
}
__device__ __forceinline__ ull fma2(ull a, ull b, ull c) {
    asm("fma.rn.f32x2 %0, %1, %2, %3;" : "=l"(c) : "l"(a), "l"(b), "l"(c));
    return c;
}
__device__ __forceinline__ ull add2(ull a, ull b) {
    ull c;
    asm("add.rn.f32x2 %0, %1, %2;" : "=l"(c) : "l"(a), "l"(b));
    return c;
}
// 128-bit shared load -> two packed f32x2 operands. volatile: must not be
// CSE'd across steps (double-buffered addresses repeat every 2 steps).
__device__ __forceinline__ void lds2(ull& a, ull& b, unsigned addr) {
    asm volatile("ld.shared.v2.u64 {%0, %1}, [%2];" : "=l"(a), "=l"(b) : "r"(addr));
}

// One warp per batch element; lane = hidden unit.
// h broadcast via double-buffered smem (8x LDS.128/step); recurrent matvec in f32x2.
__global__ void __launch_bounds__(128) rnn_step_kernel(
    const int* __restrict__ x,
    const float* __restrict__ W_hh,
    const float* __restrict__ W_fc,
    const float* __restrict__ b_fc,
    float* __restrict__ out) {

    int wl   = threadIdx.x >> 5;
    int lane = threadIdx.x & 31;
    int b    = blockIdx.x * 4 + wl;

    __shared__ __align__(16) float hbuf[4][2][HID];

    // W_hh row for this lane, packed into 16 f32x2 registers.
    ull w2[HID / 2];
#pragma unroll
    for (int j = 0; j < HID / 2; j++) {
        float2 wf = __ldg((const float2*)(W_hh + lane * HID) + j);
        w2[j] = pack2(wf.x, wf.y);
    }

    unsigned hb0 = (unsigned)__cvta_generic_to_shared(&hbuf[wl][0][0]);
    unsigned hb1 = (unsigned)__cvta_generic_to_shared(&hbuf[wl][1][0]);

    const int4* xb4 = (const int4*)(x + b * SEQ);

    hbuf[wl][0][lane] = 0.0f;
    float h = 0.0f;

    // Prime the 2-deep proj prefetch pipeline (tokens 0,1).
    int4 tc = __ldg(xb4);
    float xpA = __ldg(&g_proj[tc.x * HID + lane]);
    float xpB = __ldg(&g_proj[tc.y * HID + lane]);

#define STEP(PAR, XP, TOKPF)                                                   \
    {                                                                          \
        float xu = (XP);                                                       \
        (XP) = __ldg(&g_proj[(TOKPF) * HID + lane]); /* prefetch s+2 */        \
        __syncwarp();                                                          \
        unsigned src = (PAR) ? hb1 : hb0;                                      \
        ull p0, p1, p2, p3, p4, p5, p6, p7;                                    \
        ull a0 = 0, a1 = 0, a2 = 0, a3 = 0;                                    \
        lds2(p0, p1, src);                                                     \
        lds2(p2, p3, src + 16);                                                \
        lds2(p4, p5, src + 32);                                                \
        lds2(p6, p7, src + 48);                                                \
        a0 = fma2(p0, w2[0], a0); a1 = fma2(p1, w2[1], a1);                    \
        a2 = fma2(p2, w2[2], a2); a3 = fma2(p3, w2[3], a3);                    \
        a0 = fma2(p4, w2[4], a0); a1 = fma2(p5, w2[5], a1);                    \
        a2 = fma2(p6, w2[6], a2); a3 = fma2(p7, w2[7], a3);                    \
        lds2(p0, p1, src + 64);                                                \
        lds2(p2, p3, src + 80);                                                \
        lds2(p4, p5, src + 96);                                                \
        lds2(p6, p7, src + 112);                                               \
        a0 = fma2(p0, w2[8],  a0); a1 = fma2(p1, w2[9],  a1);                  \
        a2 = fma2(p2, w2[10], a2); a3 = fma2(p3, w2[11], a3);                  \
        a0 = fma2(p4, w2[12], a0); a1 = fma2(p5, w2[13], a1);                  \
        a2 = fma2(p6, w2[14], a2); a3 = fma2(p7, w2[15], a3);                  \
        ull ss = add2(add2(a0, a1), add2(a2, a3));                             \
        float lo, hi;                                                          \
        unpack2(ss, lo, hi);                                                   \
        h = fast_tanh(xu + lo + hi);                                           \
        hbuf[wl][(PAR) ^ 1][lane] = h;                                         \
    }

    for (int g = 0; g < SEQ / 4; g++) {
        // Next 4 tokens: one uniform-address LDG.128 per 4 steps.
        int gn = (g + 1 < SEQ / 4) ? g + 1 : g;   // clamp: last prefetches are discarded
        int4 tn = __ldg(&xb4[gn]);
        STEP(0, xpA, tc.z);   // s = 4g+0, prefetch s+2
        STEP(1, xpB, tc.w);   // s = 4g+1
        STEP(0, xpA, tn.x);   // s = 4g+2
        STEP(1, xpB, tn.y);   // s = 4g+3
        tc = tn;
    }
#undef STEP

    // Classifier head: two warp reductions.
    float v0 = h * __ldg(W_fc + lane);
    float v1 = h * __ldg(W_fc + HID + lane);
#pragma unroll
    for (int o = 16; o > 0; o >>= 1) {
        v0 += __shfl_xor_sync(0xffffffffu, v0, o);
        v1 += __shfl_xor_sync(0xffffffffu, v1, o);
    }
    if (lane == 0) {
        out[b * NCLS + 0] = v0 + __ldg(b_fc + 0);
        out[b * NCLS + 1] = v1 + __ldg(b_fc + 1);
    }
}

extern "C" void kernel_launch(void* const* d_in, const int* in_sizes, int n_in,
                              void* d_out, int out_size) {
    const int*   x    = (const int*)d_in[0];
    const float* emb  = (const float*)d_in[1];
    const float* W_ih = (const float*)d_in[2];
    const float* W_hh = (const float*)d_in[3];
    const float* b_ih = (const float*)d_in[4];
    const float* b_hh = (const float*)d_in[5];
    const float* W_fc = (const float*)d_in[6];
    const float* b_fc = (const float*)d_in[7];
    float* out = (float*)d_out;

    build_proj_kernel<<<(VOCAB + 7) / 8, 256>>>(emb, W_ih, b_ih, b_hh);
    rnn_step_kernel<<<BATCH / 4, 128>>>(x, W_hh, W_fc, b_fc, out);
}